// round 15
// baseline (speedup 1.0000x reference)
#include <cuda_runtime.h>
#include <math.h>

// ---------------- problem dims ----------------
#define BB 512
#define SS 200
#define DD 64
#define HH 2
#define HDIM 32
#define LL 2
#define BS (BB*SS)           // 102400 tokens
#define NITEMS 100000
#define IEROWS (NITEMS+1)    // 100001

// ---------------- f32x2 helpers (Blackwell packed fp32) ----------------
__device__ __forceinline__ unsigned long long pack2(float a, float b) {
    unsigned long long r;
    asm("mov.b64 %0, {%1, %2};" : "=l"(r) : "f"(a), "f"(b));
    return r;
}
__device__ __forceinline__ float2 unpack2(unsigned long long v) {
    float2 r;
    asm("mov.b64 {%0, %1}, %2;" : "=f"(r.x), "=f"(r.y) : "l"(v));
    return r;
}
__device__ __forceinline__ void fma2(unsigned long long& d,
                                     unsigned long long a, unsigned long long b) {
    asm("fma.rn.f32x2 %0, %1, %2, %0;" : "+l"(d) : "l"(a), "l"(b));
}

// ---------------- device scratch (no allocations allowed) ----------------
__device__ float g_x   [BS*DD];
__device__ float g_qin [BS*DD];
__device__ float g_q   [BS*DD];
__device__ float g_k   [BS*DD];
__device__ float g_v   [BS*DD];
__device__ float g_attn[BS*DD];
__device__ float g_h   [BS*DD];
__device__ float g_t2  [BS*DD];
__device__ float g_FF  [DD*DD];
__device__ float g_EE  [DD*DD];
__device__ float g_slots[64];   // [0]=right, [1]=item_emb sumsq, [2..31]=norm jobs

// ================= embed: x = item_emb[log]*8 + pos_emb[poss] =================
__global__ __launch_bounds__(256) void embed_kernel(
    const int* __restrict__ logs, const float* __restrict__ ie,
    const float* __restrict__ pe, float* __restrict__ x)
{
    int lane = threadIdx.x & 31;
    int gw = blockIdx.x * 8 + (threadIdx.x >> 5);
    int nw = gridDim.x * 8;
    for (int t = gw; t < BS; t += nw) {
        int s = t % SS;
        int idx = logs[t];
        int pos = idx ? (s + 1) : 0;
        float2 e = ((const float2*)(ie + (long)idx * DD))[lane];
        float2 p = ((const float2*)(pe + (long)pos * DD))[lane];
        float2 o;
        o.x = e.x * 8.0f + p.x;
        o.y = e.y * 8.0f + p.y;
        ((float2*)(x + (long)t * DD))[lane] = o;
    }
}

// ================= layernorm over last dim (64), single output =================
__global__ __launch_bounds__(256) void ln_kernel(
    const float* __restrict__ x, const float* __restrict__ w,
    const float* __restrict__ b, float* __restrict__ y)
{
    int lane = threadIdx.x & 31;
    int gw = blockIdx.x * 8 + (threadIdx.x >> 5);
    int nw = gridDim.x * 8;
    float2 wv = ((const float2*)w)[lane];
    float2 bv = ((const float2*)b)[lane];
    for (int t = gw; t < BS; t += nw) {
        float2 v = ((const float2*)(x + (long)t * DD))[lane];
        float s = v.x + v.y;
        #pragma unroll
        for (int o = 16; o; o >>= 1) s += __shfl_xor_sync(0xffffffffu, s, o);
        float m = s * (1.0f / 64.0f);
        float dx = v.x - m, dy = v.y - m;
        float q = dx * dx + dy * dy;
        #pragma unroll
        for (int o = 16; o; o >>= 1) q += __shfl_xor_sync(0xffffffffu, q, o);
        float inv = rsqrtf(q * (1.0f / 64.0f) + 1e-8f);
        float2 o2;
        o2.x = dx * inv * wv.x + bv.x;
        o2.y = dy * inv * wv.y + bv.y;
        ((float2*)(y + (long)t * DD))[lane] = o2;
    }
}

// ================= dual layernorm: y1 = LN(x;w1,b1), y2 = LN(x;w2,b2) =================
__global__ __launch_bounds__(256) void ln2_kernel(
    const float* __restrict__ x,
    const float* __restrict__ w1, const float* __restrict__ b1,
    const float* __restrict__ w2, const float* __restrict__ b2,
    float* __restrict__ y1, float* __restrict__ y2)
{
    int lane = threadIdx.x & 31;
    int gw = blockIdx.x * 8 + (threadIdx.x >> 5);
    int nw = gridDim.x * 8;
    float2 w1v = ((const float2*)w1)[lane];
    float2 b1v = ((const float2*)b1)[lane];
    float2 w2v = ((const float2*)w2)[lane];
    float2 b2v = ((const float2*)b2)[lane];
    for (int t = gw; t < BS; t += nw) {
        float2 v = ((const float2*)(x + (long)t * DD))[lane];
        float s = v.x + v.y;
        #pragma unroll
        for (int o = 16; o; o >>= 1) s += __shfl_xor_sync(0xffffffffu, s, o);
        float m = s * (1.0f / 64.0f);
        float dx = v.x - m, dy = v.y - m;
        float q = dx * dx + dy * dy;
        #pragma unroll
        for (int o = 16; o; o >>= 1) q += __shfl_xor_sync(0xffffffffu, q, o);
        float inv = rsqrtf(q * (1.0f / 64.0f) + 1e-8f);
        float nx = dx * inv, ny = dy * inv;
        float2 o1, o2;
        o1.x = nx * w1v.x + b1v.x;  o1.y = ny * w1v.y + b1v.y;
        o2.x = nx * w2v.x + b2v.x;  o2.y = ny * w2v.y + b2v.y;
        ((float2*)(y1 + (long)t * DD))[lane] = o1;
        ((float2*)(y2 + (long)t * DD))[lane] = o2;
    }
}

// ================= big GEMM: 128 tokens x (NW*64) outputs per block ==============
// out_w[t][j] = sum_d in[t][d] * Ww[j][d] + biasw[j]  (+res, relu on out0 only)
// smem: Xs transposed [64][130] (token-contiguous), Ws dup-transposed [64][132]
#define XST 130
#define WST 132
#define MM_SMEM_1 ((64*XST + 1*64*WST) * 4)
#define MM_SMEM_2 ((64*XST + 2*64*WST) * 4)

template<int NW, int RELU>
__global__ __launch_bounds__(256) void mm_big(
    const float* __restrict__ in,
    const float* __restrict__ W0, const float* __restrict__ bias0,
    const float* __restrict__ W1, const float* __restrict__ bias1,
    const float* __restrict__ res,
    float* __restrict__ out0, float* __restrict__ out1)
{
    extern __shared__ float smem[];
    float* Xs  = smem;                 // [64][XST]
    float* Ws0 = smem + 64 * XST;      // [64][WST]
    float* Ws1 = Ws0 + 64 * WST;       // [64][WST] (NW==2)

    int tid = threadIdx.x;
    long tok0 = (long)blockIdx.x * 128;

    // ---- load X tile transposed: Xs[d][t] ----
    {
        int t = tid >> 1;
        int cb = (tid & 1) * 32;
        const float* xp = in + (tok0 + t) * 64 + cb;
        #pragma unroll
        for (int kk = 0; kk < 8; kk++) {
            float4 vv = *(const float4*)(xp + 4 * kk);
            int d0 = cb + 4 * kk;
            Xs[(d0 + 0) * XST + t] = vv.x;
            Xs[(d0 + 1) * XST + t] = vv.y;
            Xs[(d0 + 2) * XST + t] = vv.z;
            Xs[(d0 + 3) * XST + t] = vv.w;
        }
    }
    // ---- load W duplicated + transposed: Ws[d][2j]=Ws[d][2j+1]=W[j][d] ----
    {
        int j  = tid & 63;
        int qb = (tid >> 6) * 16;
        #pragma unroll
        for (int kk = 0; kk < 4; kk++) {
            int d0 = qb + 4 * kk;
            float4 vv = *(const float4*)(W0 + j * 64 + d0);
            Ws0[(d0 + 0) * WST + 2 * j] = vv.x; Ws0[(d0 + 0) * WST + 2 * j + 1] = vv.x;
            Ws0[(d0 + 1) * WST + 2 * j] = vv.y; Ws0[(d0 + 1) * WST + 2 * j + 1] = vv.y;
            Ws0[(d0 + 2) * WST + 2 * j] = vv.z; Ws0[(d0 + 2) * WST + 2 * j + 1] = vv.z;
            Ws0[(d0 + 3) * WST + 2 * j] = vv.w; Ws0[(d0 + 3) * WST + 2 * j + 1] = vv.w;
            if (NW == 2) {
                float4 uu = *(const float4*)(W1 + j * 64 + d0);
                Ws1[(d0 + 0) * WST + 2 * j] = uu.x; Ws1[(d0 + 0) * WST + 2 * j + 1] = uu.x;
                Ws1[(d0 + 1) * WST + 2 * j] = uu.y; Ws1[(d0 + 1) * WST + 2 * j + 1] = uu.y;
                Ws1[(d0 + 2) * WST + 2 * j] = uu.z; Ws1[(d0 + 2) * WST + 2 * j + 1] = uu.z;
                Ws1[(d0 + 3) * WST + 2 * j] = uu.w; Ws1[(d0 + 3) * WST + 2 * j + 1] = uu.w;
            }
        }
    }
    __syncthreads();

    int tx = tid & 15, ty = tid >> 4;   // tokens 8*ty..8*ty+7, outputs 4*tx..4*tx+3
    unsigned long long acc[NW][4][4];   // [w][token-pair][output] : (lo=tok even, hi=tok odd)
    #pragma unroll
    for (int w = 0; w < NW; w++)
        #pragma unroll
        for (int p = 0; p < 4; p++)
            #pragma unroll
            for (int c = 0; c < 4; c++)
                acc[w][p][c] = 0ull;

    #pragma unroll 4
    for (int d = 0; d < 64; d++) {
        const float* xr = Xs + d * XST + 8 * ty;
        unsigned long long a[4];
        a[0] = *(const unsigned long long*)(xr + 0);
        a[1] = *(const unsigned long long*)(xr + 2);
        a[2] = *(const unsigned long long*)(xr + 4);
        a[3] = *(const unsigned long long*)(xr + 6);
        {
            const float* wr = Ws0 + d * WST + 8 * tx;
            ulonglong2 bA = *(const ulonglong2*)(wr);
            ulonglong2 bB = *(const ulonglong2*)(wr + 4);
            unsigned long long bc[4] = {bA.x, bA.y, bB.x, bB.y};
            #pragma unroll
            for (int p = 0; p < 4; p++)
                #pragma unroll
                for (int c = 0; c < 4; c++)
                    fma2(acc[0][p][c], a[p], bc[c]);
        }
        if (NW == 2) {
            const float* wr = Ws1 + d * WST + 8 * tx;
            ulonglong2 bA = *(const ulonglong2*)(wr);
            ulonglong2 bB = *(const ulonglong2*)(wr + 4);
            unsigned long long bc[4] = {bA.x, bA.y, bB.x, bB.y};
            #pragma unroll
            for (int p = 0; p < 4; p++)
                #pragma unroll
                for (int c = 0; c < 4; c++)
                    fma2(acc[1][p][c], a[p], bc[c]);
        }
    }

    // ---- epilogue ----
    float4 b4_0 = *(const float4*)(bias0 + 4 * tx);
    float4 b4_1 = (NW == 2) ? *(const float4*)(bias1 + 4 * tx)
                            : make_float4(0.f, 0.f, 0.f, 0.f);
    #pragma unroll
    for (int p = 0; p < 4; p++) {
        long tlo = tok0 + 8 * ty + 2 * p;
        float2 r0 = unpack2(acc[0][p][0]);
        float2 r1 = unpack2(acc[0][p][1]);
        float2 r2 = unpack2(acc[0][p][2]);
        float2 r3 = unpack2(acc[0][p][3]);
        float4 olo = make_float4(r0.x + b4_0.x, r1.x + b4_0.y, r2.x + b4_0.z, r3.x + b4_0.w);
        float4 ohi = make_float4(r0.y + b4_0.x, r1.y + b4_0.y, r2.y + b4_0.z, r3.y + b4_0.w);
        if (res) {
            float4 rlo = *(const float4*)(res + tlo * 64 + 4 * tx);
            float4 rhi = *(const float4*)(res + (tlo + 1) * 64 + 4 * tx);
            olo.x += rlo.x; olo.y += rlo.y; olo.z += rlo.z; olo.w += rlo.w;
            ohi.x += rhi.x; ohi.y += rhi.y; ohi.z += rhi.z; ohi.w += rhi.w;
        }
        if (RELU) {
            olo.x = fmaxf(olo.x, 0.f); olo.y = fmaxf(olo.y, 0.f);
            olo.z = fmaxf(olo.z, 0.f); olo.w = fmaxf(olo.w, 0.f);
            ohi.x = fmaxf(ohi.x, 0.f); ohi.y = fmaxf(ohi.y, 0.f);
            ohi.z = fmaxf(ohi.z, 0.f); ohi.w = fmaxf(ohi.w, 0.f);
        }
        *(float4*)(out0 + tlo * 64 + 4 * tx)       = olo;
        *(float4*)(out0 + (tlo + 1) * 64 + 4 * tx) = ohi;
        if (NW == 2) {
            float2 s0 = unpack2(acc[1][p][0]);
            float2 s1 = unpack2(acc[1][p][1]);
            float2 s2 = unpack2(acc[1][p][2]);
            float2 s3 = unpack2(acc[1][p][3]);
            float4 vlo = make_float4(s0.x + b4_1.x, s1.x + b4_1.y, s2.x + b4_1.z, s3.x + b4_1.w);
            float4 vhi = make_float4(s0.y + b4_1.x, s1.y + b4_1.y, s2.y + b4_1.z, s3.y + b4_1.w);
            *(float4*)(out1 + tlo * 64 + 4 * tx)       = vlo;
            *(float4*)(out1 + (tlo + 1) * 64 + 4 * tx) = vhi;
        }
    }
}

// ================= fused causal attention v2: 2 queries / warp pass =================
// smem: ks[200][33], vs[200][32], pr[8 warps][200][2] interleaved (p0,p1)
#define ATTN_SMEM ((200*33 + 200*32 + 8*200*2) * 4)

__global__ __launch_bounds__(256) void attn2_kernel(
    const float* __restrict__ q, const float* __restrict__ k,
    const float* __restrict__ v, float* __restrict__ o)
{
    extern __shared__ float sm[];
    float* ks = sm;                         // [200][33]
    float* vs = sm + 200 * 33;              // [200][32]
    float* pr = sm + 200 * 33 + 200 * 32;   // [8][200][2]

    int bh = blockIdx.x;
    int b = bh >> 1, h = bh & 1;
    long base = ((long)b * SS) * DD + h * HDIM;

    int tid = threadIdx.x, lane = tid & 31, w = tid >> 5;
    float* prw = pr + w * 400;

    for (int j = w; j < SS; j += 8) {
        ks[j * 33 + lane] = k[base + (long)j * DD + lane];
        vs[j * 32 + lane] = v[base + (long)j * DD + lane];
    }
    __syncthreads();

    const float scale = 0.1767766952966369f; // 1/sqrt(32)

    for (int pp = w; pp < SS / 2; pp += 8) {
        int i0 = 2 * pp, i1 = i0 + 1;

        // q rows packed as f32x2 over head-dim pairs
        unsigned long long q2a[16], q2b[16];
        const float* qp0 = q + base + (long)i0 * DD;
        #pragma unroll
        for (int dp = 0; dp < 16; dp++) {
            q2a[dp] = *(const unsigned long long*)(qp0 + 2 * dp);
            q2b[dp] = *(const unsigned long long*)(qp0 + DD + 2 * dp);
        }

        // ---- scores (each ks read feeds both queries) ----
        float mx0 = -1e30f, mx1 = -1e30f;
        for (int j = lane; j <= i1; j += 32) {
            unsigned long long s2a = 0ull, s2b = 0ull;
            const float* kr = ks + j * 33;
            #pragma unroll
            for (int dp = 0; dp < 16; dp++) {
                unsigned long long kk = pack2(kr[2 * dp], kr[2 * dp + 1]);
                fma2(s2a, q2a[dp], kk);
                fma2(s2b, q2b[dp], kk);
            }
            float2 fa = unpack2(s2a), fb = unpack2(s2b);
            float s0 = (fa.x + fa.y) * scale;
            float s1 = (fb.x + fb.y) * scale;
            if (j > i0) s0 = -1e30f;          // causal mask for query i0
            prw[2 * j]     = s0;
            prw[2 * j + 1] = s1;
            mx0 = fmaxf(mx0, s0);
            mx1 = fmaxf(mx1, s1);
        }
        #pragma unroll
        for (int oo = 16; oo; oo >>= 1) {
            mx0 = fmaxf(mx0, __shfl_xor_sync(0xffffffffu, mx0, oo));
            mx1 = fmaxf(mx1, __shfl_xor_sync(0xffffffffu, mx1, oo));
        }

        float sum0 = 0.f, sum1 = 0.f;
        for (int j = lane; j <= i1; j += 32) {
            float e0 = __expf(prw[2 * j]     - mx0);
            float e1 = __expf(prw[2 * j + 1] - mx1);
            prw[2 * j]     = e0;
            prw[2 * j + 1] = e1;
            sum0 += e0; sum1 += e1;
        }
        #pragma unroll
        for (int oo = 16; oo; oo >>= 1) {
            sum0 += __shfl_xor_sync(0xffffffffu, sum0, oo);
            sum1 += __shfl_xor_sync(0xffffffffu, sum1, oo);
        }
        float inv0 = 1.0f / sum0, inv1 = 1.0f / sum1;
        __syncwarp();

        // ---- ctx: lane = head dim; each vs read feeds both queries ----
        unsigned long long acc2 = 0ull;     // (acc_i0, acc_i1)
        for (int j = 0; j <= i1; j += 2) {  // i1 odd -> exact pairs
            float4 p4 = *(const float4*)(prw + 2 * j);  // (p0_j, p1_j, p0_j1, p1_j1)
            float va = vs[j * 32 + lane];
            float vb = vs[(j + 1) * 32 + lane];
            fma2(acc2, pack2(p4.x, p4.y), pack2(va, va));
            fma2(acc2, pack2(p4.z, p4.w), pack2(vb, vb));
        }
        float2 a2 = unpack2(acc2);
        o[base + (long)i0 * DD + lane] = a2.x * inv0;
        o[base + (long)i1 * DD + lane] = a2.y * inv1;
        __syncwarp();
    }
}

// ================= Gram: out[64][64] += sum_n X[n][i]*X[n][j] =================
__global__ __launch_bounds__(256) void gram_kernel(
    const float* __restrict__ X, int nrows, float* __restrict__ out)
{
    __shared__ float rs[32][65];
    int tid = threadIdx.x, tx = tid & 15, ty = tid >> 4;
    float acc[4][4] = {};
    int ntiles = (nrows + 31) / 32;
    for (int tile = blockIdx.x; tile < ntiles; tile += gridDim.x) {
        long r0 = (long)tile * 32;
        __syncthreads();
        #pragma unroll
        for (int kk = 0; kk < 2; kk++) {
            int e = tid + 256 * kk;
            int row = e >> 4, c4 = (e & 15) * 4;
            long gr = r0 + row;
            float4 a4 = (gr < nrows) ? *(const float4*)(X + gr * 64 + c4)
                                     : make_float4(0.f, 0.f, 0.f, 0.f);
            rs[row][c4 + 0] = a4.x; rs[row][c4 + 1] = a4.y;
            rs[row][c4 + 2] = a4.z; rs[row][c4 + 3] = a4.w;
        }
        __syncthreads();
        #pragma unroll 8
        for (int n = 0; n < 32; n++) {
            float a0 = rs[n][ty],      a1 = rs[n][ty + 16];
            float a2 = rs[n][ty + 32], a3 = rs[n][ty + 48];
            float b0 = rs[n][tx],      b1 = rs[n][tx + 16];
            float b2 = rs[n][tx + 32], b3 = rs[n][tx + 48];
            acc[0][0] += a0 * b0; acc[0][1] += a0 * b1; acc[0][2] += a0 * b2; acc[0][3] += a0 * b3;
            acc[1][0] += a1 * b0; acc[1][1] += a1 * b1; acc[1][2] += a1 * b2; acc[1][3] += a1 * b3;
            acc[2][0] += a2 * b0; acc[2][1] += a2 * b1; acc[2][2] += a2 * b2; acc[2][3] += a2 * b3;
            acc[3][0] += a3 * b0; acc[3][1] += a3 * b1; acc[3][2] += a3 * b2; acc[3][3] += a3 * b3;
        }
    }
    #pragma unroll
    for (int r = 0; r < 4; r++)
        #pragma unroll
        for (int c = 0; c < 4; c++)
            atomicAdd(out + (ty + 16 * r) * 64 + (tx + 16 * c), acc[r][c]);
}

// ================= right term =================
__global__ __launch_bounds__(256) void right_kernel(
    const float* __restrict__ x, const int* __restrict__ pos,
    const float* __restrict__ ie, const float* __restrict__ pw,
    float* __restrict__ slot)
{
    int lane = threadIdx.x & 31;
    int gw = blockIdx.x * 8 + (threadIdx.x >> 5);
    int nw = gridDim.x * 8;
    float2 pw2 = ((const float2*)pw)[lane];
    const float omc = 1.0f - 0.001f;
    float acc = 0.0f;
    for (int t = gw; t < BS; t += nw) {
        int idx = pos[t];
        float2 xv = ((const float2*)(x + (long)t * DD))[lane];
        float2 ev = ((const float2*)(ie + (long)idx * DD))[lane];
        float p = xv.x * ev.x * pw2.x + xv.y * ev.y * pw2.y;
        #pragma unroll
        for (int o = 16; o; o >>= 1) p += __shfl_xor_sync(0xffffffffu, p, o);
        if (lane == 0) acc += omc * p * p - 2.0f * p;
    }
    if (lane == 0) atomicAdd(slot, acc);
}

// ================= sum of squares (big tensor, atomic) =================
__global__ __launch_bounds__(256) void sumsq_kernel(
    const float* __restrict__ p, long n, float* __restrict__ slot)
{
    __shared__ float red[256];
    float acc = 0.0f;
    for (long i = (long)blockIdx.x * blockDim.x + threadIdx.x; i < n;
         i += (long)gridDim.x * blockDim.x) {
        float v = p[i];
        acc += v * v;
    }
    red[threadIdx.x] = acc;
    __syncthreads();
    for (int s = 128; s > 0; s >>= 1) {
        if (threadIdx.x < s) red[threadIdx.x] += red[threadIdx.x + s];
        __syncthreads();
    }
    if (threadIdx.x == 0) atomicAdd(slot, red[0]);
}

// ================= per-tensor-slice sumsq jobs (one block per job) =================
struct NJobs { const float* p[30]; int n[30]; };

__global__ __launch_bounds__(256) void normjobs_kernel(NJobs jobs, float* __restrict__ slots)
{
    __shared__ float red[256];
    int jb = blockIdx.x;
    const float* p = jobs.p[jb];
    int n = jobs.n[jb];
    float acc = 0.0f;
    for (int i = threadIdx.x; i < n; i += 256) {
        float v = p[i];
        acc += v * v;
    }
    red[threadIdx.x] = acc;
    __syncthreads();
    for (int s = 128; s > 0; s >>= 1) {
        if (threadIdx.x < s) red[threadIdx.x] += red[threadIdx.x + s];
        __syncthreads();
    }
    if (threadIdx.x == 0) slots[2 + jb] = red[0];
}

// ================= final assembly =================
__global__ __launch_bounds__(256) void final_kernel(
    const float* __restrict__ FF, const float* __restrict__ EE,
    const float* __restrict__ pw, const float* __restrict__ slots,
    float* __restrict__ out)
{
    __shared__ float red[256];
    float acc = 0.0f;
    for (int e = threadIdx.x; e < 4096; e += 256) {
        int i = e >> 6, j = e & 63;
        acc += FF[e] * EE[e] * pw[i] * pw[j];
    }
    red[threadIdx.x] = acc;
    __syncthreads();
    for (int s = 128; s > 0; s >>= 1) {
        if (threadIdx.x < s) red[threadIdx.x] += red[threadIdx.x + s];
        __syncthreads();
    }
    if (threadIdx.x == 0) {
        float left = 0.001f * red[0];
        float reg = sqrtf(slots[1]);        // item_emb
        for (int j = 2; j < 32; j++) reg += sqrtf(slots[j]);
        out[0] = left + slots[0] + 0.1f * reg;
    }
}

// ================= host launcher =================
extern "C" void kernel_launch(void* const* d_in, const int* in_sizes, int n_in,
                              void* d_out, int out_size)
{
    const int*   logs   = (const int*)d_in[1];
    const int*   posq   = (const int*)d_in[2];
    const float* ie     = (const float*)d_in[3];
    const float* pe     = (const float*)d_in[4];
    const float* pw     = (const float*)d_in[5];
    const float* ln_w   = (const float*)d_in[6];
    const float* ln_b   = (const float*)d_in[7];
    const float* qkv_w  = (const float*)d_in[8];
    const float* qkv_b  = (const float*)d_in[9];
    const float* out_w  = (const float*)d_in[10];
    const float* out_b  = (const float*)d_in[11];
    const float* fc1_w  = (const float*)d_in[12];
    const float* fc1_b  = (const float*)d_in[13];
    const float* ffln_w = (const float*)d_in[14];
    const float* ffln_b = (const float*)d_in[15];
    const float* fc2_w  = (const float*)d_in[16];
    const float* fc2_b  = (const float*)d_in[17];
    const float* ffln2_w= (const float*)d_in[18];
    const float* ffln2_b= (const float*)d_in[19];
    float* out = (float*)d_out;

    float *x, *qin, *q, *k, *v, *attn, *h, *t2, *FF, *EE, *slots;
    cudaGetSymbolAddress((void**)&x,    g_x);
    cudaGetSymbolAddress((void**)&qin,  g_qin);
    cudaGetSymbolAddress((void**)&q,    g_q);
    cudaGetSymbolAddress((void**)&k,    g_k);
    cudaGetSymbolAddress((void**)&v,    g_v);
    cudaGetSymbolAddress((void**)&attn, g_attn);
    cudaGetSymbolAddress((void**)&h,    g_h);
    cudaGetSymbolAddress((void**)&t2,   g_t2);
    cudaGetSymbolAddress((void**)&FF,   g_FF);
    cudaGetSymbolAddress((void**)&EE,   g_EE);
    cudaGetSymbolAddress((void**)&slots,g_slots);

    cudaFuncSetAttribute(attn2_kernel, cudaFuncAttributeMaxDynamicSharedMemorySize, ATTN_SMEM);
    cudaFuncSetAttribute(mm_big<1,0>,  cudaFuncAttributeMaxDynamicSharedMemorySize, MM_SMEM_1);
    cudaFuncSetAttribute(mm_big<1,1>,  cudaFuncAttributeMaxDynamicSharedMemorySize, MM_SMEM_1);
    cudaFuncSetAttribute(mm_big<2,0>,  cudaFuncAttributeMaxDynamicSharedMemorySize, MM_SMEM_2);

    cudaMemsetAsync(FF, 0, 4096 * sizeof(float));
    cudaMemsetAsync(EE, 0, 4096 * sizeof(float));
    cudaMemsetAsync(slots, 0, 64 * sizeof(float));

    embed_kernel<<<1600, 256>>>(logs, ie, pe, x);

    const int MBLK = BS / 128;   // 800
    for (int l = 0; l < LL; l++) {
        const float* Wqkv = qkv_w + (long)l * 192 * 64;
        const float* bqkv = qkv_b + (long)l * 192;

        ln_kernel<<<1600, 256>>>(x, ln_w + l * 64, ln_b + l * 64, qin);
        mm_big<1,0><<<MBLK, 256, MM_SMEM_1>>>(qin, Wqkv, bqkv,
                                              nullptr, nullptr, nullptr, q, nullptr);
        mm_big<2,0><<<MBLK, 256, MM_SMEM_2>>>(x, Wqkv + 64*64, bqkv + 64,
                                              Wqkv + 128*64, bqkv + 128, nullptr, k, v);
        attn2_kernel<<<BB * HH, 256, ATTN_SMEM>>>(q, k, v, attn);
        mm_big<1,0><<<MBLK, 256, MM_SMEM_1>>>(attn, out_w + (long)l * 4096, out_b + l * 64,
                                              nullptr, nullptr, qin, x, nullptr);
        ln2_kernel<<<1600, 256>>>(x, ffln_w + l * 64, ffln_b + l * 64,
                                  ffln2_w + l * 64, ffln2_b + l * 64, qin, t2);
        mm_big<1,1><<<MBLK, 256, MM_SMEM_1>>>(qin, fc1_w + (long)l * 4096, fc1_b + l * 64,
                                              nullptr, nullptr, nullptr, h, nullptr);
        mm_big<1,0><<<MBLK, 256, MM_SMEM_1>>>(h, fc2_w + (long)l * 4096, fc2_b + l * 64,
                                              nullptr, nullptr, t2, x, nullptr);
    }

    gram_kernel<<<256, 256>>>(x,  BS,     FF);
    gram_kernel<<<256, 256>>>(ie, IEROWS, EE);
    right_kernel<<<400, 256>>>(x, posq, ie, pw, slots);           // -> slots[0]
    sumsq_kernel<<<512, 256>>>(ie, (long)IEROWS * DD, slots + 1); // -> slots[1]

    NJobs jobs;
    int ji = 0;
    jobs.p[ji] = pe; jobs.n[ji] = (SS + 1) * DD; ji++;   // pos_emb
    jobs.p[ji] = pw; jobs.n[ji] = DD;            ji++;   // pred_w
    const float* bases[14] = {ln_w, ln_b, qkv_w, qkv_b, out_w, out_b,
                              fc1_w, fc1_b, ffln_w, ffln_b, fc2_w, fc2_b,
                              ffln2_w, ffln2_b};
    const int cnts[14] = {64, 64, 192 * 64, 192, 4096, 64, 4096, 64,
                          64, 64, 4096, 64, 64, 64};
    for (int t = 0; t < 14; t++)
        for (int l = 0; l < LL; l++) {
            jobs.p[ji] = bases[t] + (long)l * cnts[t];
            jobs.n[ji] = cnts[t];
            ji++;
        }
    normjobs_kernel<<<30, 256>>>(jobs, slots);   // -> slots[2..31]

    final_kernel<<<1, 256>>>(FF, EE, pw, slots, out);
}

// round 16
// speedup vs baseline: 1.2485x; 1.2485x over previous
#include <cuda_runtime.h>
#include <math.h>

// ---------------- problem dims ----------------
#define BB 512
#define SS 200
#define DD 64
#define HH 2
#define HDIM 32
#define LL 2
#define BS (BB*SS)           // 102400 tokens
#define NITEMS 100000
#define IEROWS (NITEMS+1)    // 100001

typedef unsigned long long ull;

// ---------------- f32x2 helpers (Blackwell packed fp32) ----------------
__device__ __forceinline__ ull pack2(float a, float b) {
    ull r;
    asm("mov.b64 %0, {%1, %2};" : "=l"(r) : "f"(a), "f"(b));
    return r;
}
__device__ __forceinline__ float2 unpack2(ull v) {
    float2 r;
    asm("mov.b64 {%0, %1}, %2;" : "=f"(r.x), "=f"(r.y) : "l"(v));
    return r;
}
__device__ __forceinline__ void fma2(ull& d, ull a, ull b) {
    asm("fma.rn.f32x2 %0, %1, %2, %0;" : "+l"(d) : "l"(a), "l"(b));
}

// ---------------- device scratch (no allocations allowed) ----------------
__device__ float g_x   [BS*DD];
__device__ float g_qin [BS*DD];
__device__ float g_q   [BS*DD];
__device__ float g_k   [BS*DD];
__device__ float g_v   [BS*DD];
__device__ float g_attn[BS*DD];
__device__ float g_h   [BS*DD];
__device__ float g_t2  [BS*DD];
__device__ float g_FF  [DD*DD];
__device__ float g_EE  [DD*DD];
__device__ float g_slots[64];   // [0]=right, [1]=item_emb sumsq, [2..31]=norm jobs

// ================= embed: x = item_emb[log]*8 + pos_emb[poss] =================
__global__ __launch_bounds__(256) void embed_kernel(
    const int* __restrict__ logs, const float* __restrict__ ie,
    const float* __restrict__ pe, float* __restrict__ x)
{
    int lane = threadIdx.x & 31;
    int gw = blockIdx.x * 8 + (threadIdx.x >> 5);
    int nw = gridDim.x * 8;
    for (int t = gw; t < BS; t += nw) {
        int s = t % SS;
        int idx = logs[t];
        int pos = idx ? (s + 1) : 0;
        float2 e = ((const float2*)(ie + (long)idx * DD))[lane];
        float2 p = ((const float2*)(pe + (long)pos * DD))[lane];
        float2 o;
        o.x = e.x * 8.0f + p.x;
        o.y = e.y * 8.0f + p.y;
        ((float2*)(x + (long)t * DD))[lane] = o;
    }
}

// ================= layernorm over last dim (64), single output =================
__global__ __launch_bounds__(256) void ln_kernel(
    const float* __restrict__ x, const float* __restrict__ w,
    const float* __restrict__ b, float* __restrict__ y)
{
    int lane = threadIdx.x & 31;
    int gw = blockIdx.x * 8 + (threadIdx.x >> 5);
    int nw = gridDim.x * 8;
    float2 wv = ((const float2*)w)[lane];
    float2 bv = ((const float2*)b)[lane];
    for (int t = gw; t < BS; t += nw) {
        float2 v = ((const float2*)(x + (long)t * DD))[lane];
        float s = v.x + v.y;
        #pragma unroll
        for (int o = 16; o; o >>= 1) s += __shfl_xor_sync(0xffffffffu, s, o);
        float m = s * (1.0f / 64.0f);
        float dx = v.x - m, dy = v.y - m;
        float q = dx * dx + dy * dy;
        #pragma unroll
        for (int o = 16; o; o >>= 1) q += __shfl_xor_sync(0xffffffffu, q, o);
        float inv = rsqrtf(q * (1.0f / 64.0f) + 1e-8f);
        float2 o2;
        o2.x = dx * inv * wv.x + bv.x;
        o2.y = dy * inv * wv.y + bv.y;
        ((float2*)(y + (long)t * DD))[lane] = o2;
    }
}

// ================= dual layernorm: y1 = LN(x;w1,b1), y2 = LN(x;w2,b2) =================
__global__ __launch_bounds__(256) void ln2_kernel(
    const float* __restrict__ x,
    const float* __restrict__ w1, const float* __restrict__ b1,
    const float* __restrict__ w2, const float* __restrict__ b2,
    float* __restrict__ y1, float* __restrict__ y2)
{
    int lane = threadIdx.x & 31;
    int gw = blockIdx.x * 8 + (threadIdx.x >> 5);
    int nw = gridDim.x * 8;
    float2 w1v = ((const float2*)w1)[lane];
    float2 b1v = ((const float2*)b1)[lane];
    float2 w2v = ((const float2*)w2)[lane];
    float2 b2v = ((const float2*)b2)[lane];
    for (int t = gw; t < BS; t += nw) {
        float2 v = ((const float2*)(x + (long)t * DD))[lane];
        float s = v.x + v.y;
        #pragma unroll
        for (int o = 16; o; o >>= 1) s += __shfl_xor_sync(0xffffffffu, s, o);
        float m = s * (1.0f / 64.0f);
        float dx = v.x - m, dy = v.y - m;
        float q = dx * dx + dy * dy;
        #pragma unroll
        for (int o = 16; o; o >>= 1) q += __shfl_xor_sync(0xffffffffu, q, o);
        float inv = rsqrtf(q * (1.0f / 64.0f) + 1e-8f);
        float nx = dx * inv, ny = dy * inv;
        float2 o1, o2;
        o1.x = nx * w1v.x + b1v.x;  o1.y = ny * w1v.y + b1v.y;
        o2.x = nx * w2v.x + b2v.x;  o2.y = ny * w2v.y + b2v.y;
        ((float2*)(y1 + (long)t * DD))[lane] = o1;
        ((float2*)(y2 + (long)t * DD))[lane] = o2;
    }
}

// ================= GEMM v3: 128 tokens x 64 outputs, f32x2, no W-dup ==============
// Xs transposed [64][XST] (token pairs contiguous -> LDS.64 broadcast)
// Ws transposed [64][WTS] un-duplicated -> one conflict-free LDS.128 per thread per d
#define XST 130
#define WTS 68
#define MM_SMEM ((64*XST + 64*WTS) * 4)

template<int RELU>
__global__ void __launch_bounds__(256, 3) mm_t(
    const float* __restrict__ in, const float* __restrict__ W,
    const float* __restrict__ bias, const float* __restrict__ res,
    float* __restrict__ out)
{
    extern __shared__ float smem[];
    float* Xs = smem;              // [64][XST] : Xs[d][t]
    float* Ws = smem + 64 * XST;   // [64][WTS] : Ws[d][j]

    int tid = threadIdx.x;
    long tok0 = (long)blockIdx.x * 128;

    // ---- load X tile transposed: Xs[d][t] ----
    {
        int t  = tid >> 1;
        int cb = (tid & 1) * 32;
        const float* xp = in + (tok0 + t) * 64 + cb;
        #pragma unroll
        for (int kk = 0; kk < 8; kk++) {
            float4 vv = *(const float4*)(xp + 4 * kk);
            int d0 = cb + 4 * kk;
            Xs[(d0 + 0) * XST + t] = vv.x;
            Xs[(d0 + 1) * XST + t] = vv.y;
            Xs[(d0 + 2) * XST + t] = vv.z;
            Xs[(d0 + 3) * XST + t] = vv.w;
        }
    }
    // ---- load W transposed (no duplication): Ws[d][j] = W[j][d] ----
    {
        int j  = tid & 63;
        int db = (tid >> 6) * 16;
        #pragma unroll
        for (int kk = 0; kk < 4; kk++) {
            int d0 = db + 4 * kk;
            float4 vv = *(const float4*)(W + j * 64 + d0);
            Ws[(d0 + 0) * WTS + j] = vv.x;
            Ws[(d0 + 1) * WTS + j] = vv.y;
            Ws[(d0 + 2) * WTS + j] = vv.z;
            Ws[(d0 + 3) * WTS + j] = vv.w;
        }
    }
    __syncthreads();

    int tx = tid & 15, ty = tid >> 4;   // tokens 8*ty..8*ty+7 (4 pairs), outputs 4*tx..4*tx+3
    ull acc[4][4];
    #pragma unroll
    for (int p = 0; p < 4; p++)
        #pragma unroll
        for (int c = 0; c < 4; c++)
            acc[p][c] = 0ull;

    #pragma unroll 4
    for (int d = 0; d < 64; d++) {
        const float* xr = Xs + d * XST + 8 * ty;
        ull a0 = *(const ull*)(xr + 0);
        ull a1 = *(const ull*)(xr + 2);
        ull a2 = *(const ull*)(xr + 4);
        ull a3 = *(const ull*)(xr + 6);
        float4 bw = *(const float4*)(Ws + d * WTS + 4 * tx);
        ull b0 = pack2(bw.x, bw.x);
        ull b1 = pack2(bw.y, bw.y);
        ull b2 = pack2(bw.z, bw.z);
        ull b3 = pack2(bw.w, bw.w);
        fma2(acc[0][0], a0, b0); fma2(acc[0][1], a0, b1); fma2(acc[0][2], a0, b2); fma2(acc[0][3], a0, b3);
        fma2(acc[1][0], a1, b0); fma2(acc[1][1], a1, b1); fma2(acc[1][2], a1, b2); fma2(acc[1][3], a1, b3);
        fma2(acc[2][0], a2, b0); fma2(acc[2][1], a2, b1); fma2(acc[2][2], a2, b2); fma2(acc[2][3], a2, b3);
        fma2(acc[3][0], a3, b0); fma2(acc[3][1], a3, b1); fma2(acc[3][2], a3, b2); fma2(acc[3][3], a3, b3);
    }

    // ---- epilogue ----
    float4 b4 = *(const float4*)(bias + 4 * tx);
    #pragma unroll
    for (int p = 0; p < 4; p++) {
        long tlo = tok0 + 8 * ty + 2 * p;
        float2 r0 = unpack2(acc[p][0]);
        float2 r1 = unpack2(acc[p][1]);
        float2 r2 = unpack2(acc[p][2]);
        float2 r3 = unpack2(acc[p][3]);
        float4 olo = make_float4(r0.x + b4.x, r1.x + b4.y, r2.x + b4.z, r3.x + b4.w);
        float4 ohi = make_float4(r0.y + b4.x, r1.y + b4.y, r2.y + b4.z, r3.y + b4.w);
        if (res) {
            float4 rlo = *(const float4*)(res + tlo * 64 + 4 * tx);
            float4 rhi = *(const float4*)(res + (tlo + 1) * 64 + 4 * tx);
            olo.x += rlo.x; olo.y += rlo.y; olo.z += rlo.z; olo.w += rlo.w;
            ohi.x += rhi.x; ohi.y += rhi.y; ohi.z += rhi.z; ohi.w += rhi.w;
        }
        if (RELU) {
            olo.x = fmaxf(olo.x, 0.f); olo.y = fmaxf(olo.y, 0.f);
            olo.z = fmaxf(olo.z, 0.f); olo.w = fmaxf(olo.w, 0.f);
            ohi.x = fmaxf(ohi.x, 0.f); ohi.y = fmaxf(ohi.y, 0.f);
            ohi.z = fmaxf(ohi.z, 0.f); ohi.w = fmaxf(ohi.w, 0.f);
        }
        *(float4*)(out + tlo * 64 + 4 * tx)       = olo;
        *(float4*)(out + (tlo + 1) * 64 + 4 * tx) = ohi;
    }
}

// ================= fused causal attention: 2 queries / warp pass =================
// ks padded to stride 34 so rows are 8B-aligned -> direct LDS.64 q.k pairs
#define ATTN_SMEM ((200*34 + 200*32 + 8*200*2) * 4)

__global__ __launch_bounds__(256) void attn2_kernel(
    const float* __restrict__ q, const float* __restrict__ k,
    const float* __restrict__ v, float* __restrict__ o)
{
    extern __shared__ float sm[];
    float* ks = sm;                         // [200][34]
    float* vs = sm + 200 * 34;              // [200][32]
    float* pr = sm + 200 * 34 + 200 * 32;   // [8][200][2]

    int bh = blockIdx.x;
    int b = bh >> 1, h = bh & 1;
    long base = ((long)b * SS) * DD + h * HDIM;

    int tid = threadIdx.x, lane = tid & 31, w = tid >> 5;
    float* prw = pr + w * 400;

    for (int j = w; j < SS; j += 8) {
        ks[j * 34 + lane] = k[base + (long)j * DD + lane];
        vs[j * 32 + lane] = v[base + (long)j * DD + lane];
    }
    __syncthreads();

    const float scale = 0.1767766952966369f; // 1/sqrt(32)

    for (int pp = w; pp < SS / 2; pp += 8) {
        int i0 = 2 * pp, i1 = i0 + 1;

        // q rows packed as f32x2 over head-dim pairs
        ull q2a[16], q2b[16];
        const float* qp0 = q + base + (long)i0 * DD;
        #pragma unroll
        for (int dp = 0; dp < 16; dp++) {
            q2a[dp] = *(const ull*)(qp0 + 2 * dp);
            q2b[dp] = *(const ull*)(qp0 + DD + 2 * dp);
        }

        // ---- scores (each ks read feeds both queries) ----
        float mx0 = -1e30f, mx1 = -1e30f;
        for (int j = lane; j <= i1; j += 32) {
            ull s2a = 0ull, s2b = 0ull;
            const float* kr = ks + j * 34;
            #pragma unroll
            for (int dp = 0; dp < 16; dp++) {
                ull kk = *(const ull*)(kr + 2 * dp);   // 8B-aligned (stride 34)
                fma2(s2a, q2a[dp], kk);
                fma2(s2b, q2b[dp], kk);
            }
            float2 fa = unpack2(s2a), fb = unpack2(s2b);
            float s0 = (fa.x + fa.y) * scale;
            float s1 = (fb.x + fb.y) * scale;
            if (j > i0) s0 = -1e30f;          // causal mask for query i0
            prw[2 * j]     = s0;
            prw[2 * j + 1] = s1;
            mx0 = fmaxf(mx0, s0);
            mx1 = fmaxf(mx1, s1);
        }
        #pragma unroll
        for (int oo = 16; oo; oo >>= 1) {
            mx0 = fmaxf(mx0, __shfl_xor_sync(0xffffffffu, mx0, oo));
            mx1 = fmaxf(mx1, __shfl_xor_sync(0xffffffffu, mx1, oo));
        }

        float sum0 = 0.f, sum1 = 0.f;
        for (int j = lane; j <= i1; j += 32) {
            float e0 = __expf(prw[2 * j]     - mx0);
            float e1 = __expf(prw[2 * j + 1] - mx1);
            prw[2 * j]     = e0;
            prw[2 * j + 1] = e1;
            sum0 += e0; sum1 += e1;
        }
        #pragma unroll
        for (int oo = 16; oo; oo >>= 1) {
            sum0 += __shfl_xor_sync(0xffffffffu, sum0, oo);
            sum1 += __shfl_xor_sync(0xffffffffu, sum1, oo);
        }
        float inv0 = 1.0f / sum0, inv1 = 1.0f / sum1;
        __syncwarp();

        // ---- ctx: lane = head dim; each vs read feeds both queries ----
        ull acc2 = 0ull;                    // (acc_i0, acc_i1)
        for (int j = 0; j <= i1; j += 2) {  // i1 odd -> exact pairs
            float4 p4 = *(const float4*)(prw + 2 * j);  // (p0_j, p1_j, p0_j1, p1_j1)
            float va = vs[j * 32 + lane];
            float vb = vs[(j + 1) * 32 + lane];
            fma2(acc2, pack2(p4.x, p4.y), pack2(va, va));
            fma2(acc2, pack2(p4.z, p4.w), pack2(vb, vb));
        }
        float2 a2 = unpack2(acc2);
        o[base + (long)i0 * DD + lane] = a2.x * inv0;
        o[base + (long)i1 * DD + lane] = a2.y * inv1;
        __syncwarp();
    }
}

// ================= Gram: out[64][64] += sum_n X[n][i]*X[n][j] =================
__global__ __launch_bounds__(256) void gram_kernel(
    const float* __restrict__ X, int nrows, float* __restrict__ out)
{
    __shared__ float rs[32][65];
    int tid = threadIdx.x, tx = tid & 15, ty = tid >> 4;
    float acc[4][4] = {};
    int ntiles = (nrows + 31) / 32;
    for (int tile = blockIdx.x; tile < ntiles; tile += gridDim.x) {
        long r0 = (long)tile * 32;
        __syncthreads();
        #pragma unroll
        for (int kk = 0; kk < 2; kk++) {
            int e = tid + 256 * kk;
            int row = e >> 4, c4 = (e & 15) * 4;
            long gr = r0 + row;
            float4 a4 = (gr < nrows) ? *(const float4*)(X + gr * 64 + c4)
                                     : make_float4(0.f, 0.f, 0.f, 0.f);
            rs[row][c4 + 0] = a4.x; rs[row][c4 + 1] = a4.y;
            rs[row][c4 + 2] = a4.z; rs[row][c4 + 3] = a4.w;
        }
        __syncthreads();
        #pragma unroll 8
        for (int n = 0; n < 32; n++) {
            float a0 = rs[n][ty],      a1 = rs[n][ty + 16];
            float a2 = rs[n][ty + 32], a3 = rs[n][ty + 48];
            float b0 = rs[n][tx],      b1 = rs[n][tx + 16];
            float b2 = rs[n][tx + 32], b3 = rs[n][tx + 48];
            acc[0][0] += a0 * b0; acc[0][1] += a0 * b1; acc[0][2] += a0 * b2; acc[0][3] += a0 * b3;
            acc[1][0] += a1 * b0; acc[1][1] += a1 * b1; acc[1][2] += a1 * b2; acc[1][3] += a1 * b3;
            acc[2][0] += a2 * b0; acc[2][1] += a2 * b1; acc[2][2] += a2 * b2; acc[2][3] += a2 * b3;
            acc[3][0] += a3 * b0; acc[3][1] += a3 * b1; acc[3][2] += a3 * b2; acc[3][3] += a3 * b3;
        }
    }
    #pragma unroll
    for (int r = 0; r < 4; r++)
        #pragma unroll
        for (int c = 0; c < 4; c++)
            atomicAdd(out + (ty + 16 * r) * 64 + (tx + 16 * c), acc[r][c]);
}

// ================= right term =================
__global__ __launch_bounds__(256) void right_kernel(
    const float* __restrict__ x, const int* __restrict__ pos,
    const float* __restrict__ ie, const float* __restrict__ pw,
    float* __restrict__ slot)
{
    int lane = threadIdx.x & 31;
    int gw = blockIdx.x * 8 + (threadIdx.x >> 5);
    int nw = gridDim.x * 8;
    float2 pw2 = ((const float2*)pw)[lane];
    const float omc = 1.0f - 0.001f;
    float acc = 0.0f;
    for (int t = gw; t < BS; t += nw) {
        int idx = pos[t];
        float2 xv = ((const float2*)(x + (long)t * DD))[lane];
        float2 ev = ((const float2*)(ie + (long)idx * DD))[lane];
        float p = xv.x * ev.x * pw2.x + xv.y * ev.y * pw2.y;
        #pragma unroll
        for (int o = 16; o; o >>= 1) p += __shfl_xor_sync(0xffffffffu, p, o);
        if (lane == 0) acc += omc * p * p - 2.0f * p;
    }
    if (lane == 0) atomicAdd(slot, acc);
}

// ================= sum of squares (big tensor, atomic) =================
__global__ __launch_bounds__(256) void sumsq_kernel(
    const float* __restrict__ p, long n, float* __restrict__ slot)
{
    __shared__ float red[256];
    float acc = 0.0f;
    for (long i = (long)blockIdx.x * blockDim.x + threadIdx.x; i < n;
         i += (long)gridDim.x * blockDim.x) {
        float v = p[i];
        acc += v * v;
    }
    red[threadIdx.x] = acc;
    __syncthreads();
    for (int s = 128; s > 0; s >>= 1) {
        if (threadIdx.x < s) red[threadIdx.x] += red[threadIdx.x + s];
        __syncthreads();
    }
    if (threadIdx.x == 0) atomicAdd(slot, red[0]);
}

// ================= per-tensor-slice sumsq jobs (one block per job) =================
struct NJobs { const float* p[30]; int n[30]; };

__global__ __launch_bounds__(256) void normjobs_kernel(NJobs jobs, float* __restrict__ slots)
{
    __shared__ float red[256];
    int jb = blockIdx.x;
    const float* p = jobs.p[jb];
    int n = jobs.n[jb];
    float acc = 0.0f;
    for (int i = threadIdx.x; i < n; i += 256) {
        float v = p[i];
        acc += v * v;
    }
    red[threadIdx.x] = acc;
    __syncthreads();
    for (int s = 128; s > 0; s >>= 1) {
        if (threadIdx.x < s) red[threadIdx.x] += red[threadIdx.x + s];
        __syncthreads();
    }
    if (threadIdx.x == 0) slots[2 + jb] = red[0];
}

// ================= final assembly =================
__global__ __launch_bounds__(256) void final_kernel(
    const float* __restrict__ FF, const float* __restrict__ EE,
    const float* __restrict__ pw, const float* __restrict__ slots,
    float* __restrict__ out)
{
    __shared__ float red[256];
    float acc = 0.0f;
    for (int e = threadIdx.x; e < 4096; e += 256) {
        int i = e >> 6, j = e & 63;
        acc += FF[e] * EE[e] * pw[i] * pw[j];
    }
    red[threadIdx.x] = acc;
    __syncthreads();
    for (int s = 128; s > 0; s >>= 1) {
        if (threadIdx.x < s) red[threadIdx.x] += red[threadIdx.x + s];
        __syncthreads();
    }
    if (threadIdx.x == 0) {
        float left = 0.001f * red[0];
        float reg = sqrtf(slots[1]);        // item_emb
        for (int j = 2; j < 32; j++) reg += sqrtf(slots[j]);
        out[0] = left + slots[0] + 0.1f * reg;
    }
}

// ================= host launcher =================
extern "C" void kernel_launch(void* const* d_in, const int* in_sizes, int n_in,
                              void* d_out, int out_size)
{
    const int*   logs   = (const int*)d_in[1];
    const int*   posq   = (const int*)d_in[2];
    const float* ie     = (const float*)d_in[3];
    const float* pe     = (const float*)d_in[4];
    const float* pw     = (const float*)d_in[5];
    const float* ln_w   = (const float*)d_in[6];
    const float* ln_b   = (const float*)d_in[7];
    const float* qkv_w  = (const float*)d_in[8];
    const float* qkv_b  = (const float*)d_in[9];
    const float* out_w  = (const float*)d_in[10];
    const float* out_b  = (const float*)d_in[11];
    const float* fc1_w  = (const float*)d_in[12];
    const float* fc1_b  = (const float*)d_in[13];
    const float* ffln_w = (const float*)d_in[14];
    const float* ffln_b = (const float*)d_in[15];
    const float* fc2_w  = (const float*)d_in[16];
    const float* fc2_b  = (const float*)d_in[17];
    const float* ffln2_w= (const float*)d_in[18];
    const float* ffln2_b= (const float*)d_in[19];
    float* out = (float*)d_out;

    float *x, *qin, *q, *k, *v, *attn, *h, *t2, *FF, *EE, *slots;
    cudaGetSymbolAddress((void**)&x,    g_x);
    cudaGetSymbolAddress((void**)&qin,  g_qin);
    cudaGetSymbolAddress((void**)&q,    g_q);
    cudaGetSymbolAddress((void**)&k,    g_k);
    cudaGetSymbolAddress((void**)&v,    g_v);
    cudaGetSymbolAddress((void**)&attn, g_attn);
    cudaGetSymbolAddress((void**)&h,    g_h);
    cudaGetSymbolAddress((void**)&t2,   g_t2);
    cudaGetSymbolAddress((void**)&FF,   g_FF);
    cudaGetSymbolAddress((void**)&EE,   g_EE);
    cudaGetSymbolAddress((void**)&slots,g_slots);

    cudaFuncSetAttribute(attn2_kernel, cudaFuncAttributeMaxDynamicSharedMemorySize, ATTN_SMEM);
    cudaFuncSetAttribute(mm_t<0>, cudaFuncAttributeMaxDynamicSharedMemorySize, MM_SMEM);
    cudaFuncSetAttribute(mm_t<1>, cudaFuncAttributeMaxDynamicSharedMemorySize, MM_SMEM);

    cudaMemsetAsync(FF, 0, 4096 * sizeof(float));
    cudaMemsetAsync(EE, 0, 4096 * sizeof(float));
    cudaMemsetAsync(slots, 0, 64 * sizeof(float));

    embed_kernel<<<1600, 256>>>(logs, ie, pe, x);

    const int MBLK = BS / 128;   // 800
    for (int l = 0; l < LL; l++) {
        const float* Wqkv = qkv_w + (long)l * 192 * 64;
        const float* bqkv = qkv_b + (long)l * 192;

        ln_kernel<<<1600, 256>>>(x, ln_w + l * 64, ln_b + l * 64, qin);
        mm_t<0><<<MBLK, 256, MM_SMEM>>>(qin, Wqkv,            bqkv,       nullptr, q);
        mm_t<0><<<MBLK, 256, MM_SMEM>>>(x,   Wqkv + 64 * 64,  bqkv + 64,  nullptr, k);
        mm_t<0><<<MBLK, 256, MM_SMEM>>>(x,   Wqkv + 128 * 64, bqkv + 128, nullptr, v);
        attn2_kernel<<<BB * HH, 256, ATTN_SMEM>>>(q, k, v, attn);
        mm_t<0><<<MBLK, 256, MM_SMEM>>>(attn, out_w + (long)l * 4096, out_b + l * 64, qin, x);
        ln2_kernel<<<1600, 256>>>(x, ffln_w + l * 64, ffln_b + l * 64,
                                  ffln2_w + l * 64, ffln2_b + l * 64, qin, t2);
        mm_t<1><<<MBLK, 256, MM_SMEM>>>(qin, fc1_w + (long)l * 4096, fc1_b + l * 64, nullptr, h);
        mm_t<0><<<MBLK, 256, MM_SMEM>>>(h,   fc2_w + (long)l * 4096, fc2_b + l * 64, t2, x);
    }

    gram_kernel<<<256, 256>>>(x,  BS,     FF);
    gram_kernel<<<256, 256>>>(ie, IEROWS, EE);
    right_kernel<<<400, 256>>>(x, posq, ie, pw, slots);           // -> slots[0]
    sumsq_kernel<<<512, 256>>>(ie, (long)IEROWS * DD, slots + 1); // -> slots[1]

    NJobs jobs;
    int ji = 0;
    jobs.p[ji] = pe; jobs.n[ji] = (SS + 1) * DD; ji++;   // pos_emb
    jobs.p[ji] = pw; jobs.n[ji] = DD;            ji++;   // pred_w
    const float* bases[14] = {ln_w, ln_b, qkv_w, qkv_b, out_w, out_b,
                              fc1_w, fc1_b, ffln_w, ffln_b, fc2_w, fc2_b,
                              ffln2_w, ffln2_b};
    const int cnts[14] = {64, 64, 192 * 64, 192, 4096, 64, 4096, 64,
                          64, 64, 4096, 64, 64, 64};
    for (int t = 0; t < 14; t++)
        for (int l = 0; l < LL; l++) {
            jobs.p[ji] = bases[t] + (long)l * cnts[t];
            jobs.n[ji] = cnts[t];
            ji++;
        }
    normjobs_kernel<<<30, 256>>>(jobs, slots);   // -> slots[2..31]

    final_kernel<<<1, 256>>>(FF, EE, pw, slots, out);
}

// round 17
// speedup vs baseline: 1.2551x; 1.0053x over previous
#include <cuda_runtime.h>
#include <math.h>

// ---------------- problem dims ----------------
#define BB 512
#define SS 200
#define DD 64
#define HH 2
#define HDIM 32
#define LL 2
#define BS (BB*SS)           // 102400 tokens
#define NITEMS 100000
#define IEROWS (NITEMS+1)    // 100001

typedef unsigned long long ull;

// ---------------- f32x2 helpers (Blackwell packed fp32) ----------------
__device__ __forceinline__ ull pack2(float a, float b) {
    ull r;
    asm("mov.b64 %0, {%1, %2};" : "=l"(r) : "f"(a), "f"(b));
    return r;
}
__device__ __forceinline__ float2 unpack2(ull v) {
    float2 r;
    asm("mov.b64 {%0, %1}, %2;" : "=f"(r.x), "=f"(r.y) : "l"(v));
    return r;
}
__device__ __forceinline__ void fma2(ull& d, ull a, ull b) {
    asm("fma.rn.f32x2 %0, %1, %2, %0;" : "+l"(d) : "l"(a), "l"(b));
}

// ---------------- device scratch (no allocations allowed) ----------------
__device__ float g_x   [BS*DD];
__device__ float g_qin [BS*DD];
__device__ float g_q   [BS*DD];
__device__ float g_k   [BS*DD];
__device__ float g_v   [BS*DD];
__device__ float g_attn[BS*DD];
__device__ float g_h   [BS*DD];
__device__ float g_t2  [BS*DD];
__device__ float g_FF  [DD*DD];
__device__ float g_EE  [DD*DD];
__device__ float g_slots[64];   // [0]=right, [1]=item_emb sumsq, [2..31]=norm jobs

// ================= embed: x = item_emb[log]*8 + pos_emb[poss] =================
__global__ __launch_bounds__(256) void embed_kernel(
    const int* __restrict__ logs, const float* __restrict__ ie,
    const float* __restrict__ pe, float* __restrict__ x)
{
    int lane = threadIdx.x & 31;
    int gw = blockIdx.x * 8 + (threadIdx.x >> 5);
    int nw = gridDim.x * 8;
    for (int t = gw; t < BS; t += nw) {
        int s = t % SS;
        int idx = logs[t];
        int pos = idx ? (s + 1) : 0;
        float2 e = ((const float2*)(ie + (long)idx * DD))[lane];
        float2 p = ((const float2*)(pe + (long)pos * DD))[lane];
        float2 o;
        o.x = e.x * 8.0f + p.x;
        o.y = e.y * 8.0f + p.y;
        ((float2*)(x + (long)t * DD))[lane] = o;
    }
}

// ================= layernorm over last dim (64), single output =================
__global__ __launch_bounds__(256) void ln_kernel(
    const float* __restrict__ x, const float* __restrict__ w,
    const float* __restrict__ b, float* __restrict__ y)
{
    int lane = threadIdx.x & 31;
    int gw = blockIdx.x * 8 + (threadIdx.x >> 5);
    int nw = gridDim.x * 8;
    float2 wv = ((const float2*)w)[lane];
    float2 bv = ((const float2*)b)[lane];
    for (int t = gw; t < BS; t += nw) {
        float2 v = ((const float2*)(x + (long)t * DD))[lane];
        float s = v.x + v.y;
        #pragma unroll
        for (int o = 16; o; o >>= 1) s += __shfl_xor_sync(0xffffffffu, s, o);
        float m = s * (1.0f / 64.0f);
        float dx = v.x - m, dy = v.y - m;
        float q = dx * dx + dy * dy;
        #pragma unroll
        for (int o = 16; o; o >>= 1) q += __shfl_xor_sync(0xffffffffu, q, o);
        float inv = rsqrtf(q * (1.0f / 64.0f) + 1e-8f);
        float2 o2;
        o2.x = dx * inv * wv.x + bv.x;
        o2.y = dy * inv * wv.y + bv.y;
        ((float2*)(y + (long)t * DD))[lane] = o2;
    }
}

// ================= dual layernorm: y1 = LN(x;w1,b1), y2 = LN(x;w2,b2) =================
__global__ __launch_bounds__(256) void ln2_kernel(
    const float* __restrict__ x,
    const float* __restrict__ w1, const float* __restrict__ b1,
    const float* __restrict__ w2, const float* __restrict__ b2,
    float* __restrict__ y1, float* __restrict__ y2)
{
    int lane = threadIdx.x & 31;
    int gw = blockIdx.x * 8 + (threadIdx.x >> 5);
    int nw = gridDim.x * 8;
    float2 w1v = ((const float2*)w1)[lane];
    float2 b1v = ((const float2*)b1)[lane];
    float2 w2v = ((const float2*)w2)[lane];
    float2 b2v = ((const float2*)b2)[lane];
    for (int t = gw; t < BS; t += nw) {
        float2 v = ((const float2*)(x + (long)t * DD))[lane];
        float s = v.x + v.y;
        #pragma unroll
        for (int o = 16; o; o >>= 1) s += __shfl_xor_sync(0xffffffffu, s, o);
        float m = s * (1.0f / 64.0f);
        float dx = v.x - m, dy = v.y - m;
        float q = dx * dx + dy * dy;
        #pragma unroll
        for (int o = 16; o; o >>= 1) q += __shfl_xor_sync(0xffffffffu, q, o);
        float inv = rsqrtf(q * (1.0f / 64.0f) + 1e-8f);
        float nx = dx * inv, ny = dy * inv;
        float2 o1, o2;
        o1.x = nx * w1v.x + b1v.x;  o1.y = ny * w1v.y + b1v.y;
        o2.x = nx * w2v.x + b2v.x;  o2.y = ny * w2v.y + b2v.y;
        ((float2*)(y1 + (long)t * DD))[lane] = o1;
        ((float2*)(y2 + (long)t * DD))[lane] = o2;
    }
}

// ================= GEMM v3: 128 tokens x 64 outputs, f32x2, no W-dup ==============
// Xs transposed [64][XST] (token pairs contiguous -> LDS.64 broadcast)
// Ws transposed [64][WTS] un-duplicated -> one conflict-free LDS.128 per thread per d
#define XST 130
#define WTS 68
#define MM_SMEM ((64*XST + 64*WTS) * 4)

template<int RELU>
__global__ void __launch_bounds__(256, 3) mm_t(
    const float* __restrict__ in, const float* __restrict__ W,
    const float* __restrict__ bias, const float* __restrict__ res,
    float* __restrict__ out)
{
    extern __shared__ float smem[];
    float* Xs = smem;              // [64][XST] : Xs[d][t]
    float* Ws = smem + 64 * XST;   // [64][WTS] : Ws[d][j]

    int tid = threadIdx.x;
    long tok0 = (long)blockIdx.x * 128;

    // ---- load X tile transposed: Xs[d][t] ----
    {
        int t  = tid >> 1;
        int cb = (tid & 1) * 32;
        const float* xp = in + (tok0 + t) * 64 + cb;
        #pragma unroll
        for (int kk = 0; kk < 8; kk++) {
            float4 vv = *(const float4*)(xp + 4 * kk);
            int d0 = cb + 4 * kk;
            Xs[(d0 + 0) * XST + t] = vv.x;
            Xs[(d0 + 1) * XST + t] = vv.y;
            Xs[(d0 + 2) * XST + t] = vv.z;
            Xs[(d0 + 3) * XST + t] = vv.w;
        }
    }
    // ---- load W transposed (no duplication): Ws[d][j] = W[j][d] ----
    {
        int j  = tid & 63;
        int db = (tid >> 6) * 16;
        #pragma unroll
        for (int kk = 0; kk < 4; kk++) {
            int d0 = db + 4 * kk;
            float4 vv = *(const float4*)(W + j * 64 + d0);
            Ws[(d0 + 0) * WTS + j] = vv.x;
            Ws[(d0 + 1) * WTS + j] = vv.y;
            Ws[(d0 + 2) * WTS + j] = vv.z;
            Ws[(d0 + 3) * WTS + j] = vv.w;
        }
    }
    __syncthreads();

    int tx = tid & 15, ty = tid >> 4;   // tokens 8*ty..8*ty+7 (4 pairs), outputs 4*tx..4*tx+3
    ull acc[4][4];
    #pragma unroll
    for (int p = 0; p < 4; p++)
        #pragma unroll
        for (int c = 0; c < 4; c++)
            acc[p][c] = 0ull;

    #pragma unroll 4
    for (int d = 0; d < 64; d++) {
        const float* xr = Xs + d * XST + 8 * ty;
        ull a0 = *(const ull*)(xr + 0);
        ull a1 = *(const ull*)(xr + 2);
        ull a2 = *(const ull*)(xr + 4);
        ull a3 = *(const ull*)(xr + 6);
        float4 bw = *(const float4*)(Ws + d * WTS + 4 * tx);
        ull b0 = pack2(bw.x, bw.x);
        ull b1 = pack2(bw.y, bw.y);
        ull b2 = pack2(bw.z, bw.z);
        ull b3 = pack2(bw.w, bw.w);
        fma2(acc[0][0], a0, b0); fma2(acc[0][1], a0, b1); fma2(acc[0][2], a0, b2); fma2(acc[0][3], a0, b3);
        fma2(acc[1][0], a1, b0); fma2(acc[1][1], a1, b1); fma2(acc[1][2], a1, b2); fma2(acc[1][3], a1, b3);
        fma2(acc[2][0], a2, b0); fma2(acc[2][1], a2, b1); fma2(acc[2][2], a2, b2); fma2(acc[2][3], a2, b3);
        fma2(acc[3][0], a3, b0); fma2(acc[3][1], a3, b1); fma2(acc[3][2], a3, b2); fma2(acc[3][3], a3, b3);
    }

    // ---- epilogue ----
    float4 b4 = *(const float4*)(bias + 4 * tx);
    #pragma unroll
    for (int p = 0; p < 4; p++) {
        long tlo = tok0 + 8 * ty + 2 * p;
        float2 r0 = unpack2(acc[p][0]);
        float2 r1 = unpack2(acc[p][1]);
        float2 r2 = unpack2(acc[p][2]);
        float2 r3 = unpack2(acc[p][3]);
        float4 olo = make_float4(r0.x + b4.x, r1.x + b4.y, r2.x + b4.z, r3.x + b4.w);
        float4 ohi = make_float4(r0.y + b4.x, r1.y + b4.y, r2.y + b4.z, r3.y + b4.w);
        if (res) {
            float4 rlo = *(const float4*)(res + tlo * 64 + 4 * tx);
            float4 rhi = *(const float4*)(res + (tlo + 1) * 64 + 4 * tx);
            olo.x += rlo.x; olo.y += rlo.y; olo.z += rlo.z; olo.w += rlo.w;
            ohi.x += rhi.x; ohi.y += rhi.y; ohi.z += rhi.z; ohi.w += rhi.w;
        }
        if (RELU) {
            olo.x = fmaxf(olo.x, 0.f); olo.y = fmaxf(olo.y, 0.f);
            olo.z = fmaxf(olo.z, 0.f); olo.w = fmaxf(olo.w, 0.f);
            ohi.x = fmaxf(ohi.x, 0.f); ohi.y = fmaxf(ohi.y, 0.f);
            ohi.z = fmaxf(ohi.z, 0.f); ohi.w = fmaxf(ohi.w, 0.f);
        }
        *(float4*)(out + tlo * 64 + 4 * tx)       = olo;
        *(float4*)(out + (tlo + 1) * 64 + 4 * tx) = ohi;
    }
}

// ================= fused causal attention: 2 queries / warp pass =================
// ks padded to stride 34 so rows are 8B-aligned -> direct LDS.64 q.k pairs
#define ATTN_SMEM ((200*34 + 200*32 + 8*200*2) * 4)

__global__ __launch_bounds__(256) void attn2_kernel(
    const float* __restrict__ q, const float* __restrict__ k,
    const float* __restrict__ v, float* __restrict__ o)
{
    extern __shared__ float sm[];
    float* ks = sm;                         // [200][34]
    float* vs = sm + 200 * 34;              // [200][32]
    float* pr = sm + 200 * 34 + 200 * 32;   // [8][200][2]

    int bh = blockIdx.x;
    int b = bh >> 1, h = bh & 1;
    long base = ((long)b * SS) * DD + h * HDIM;

    int tid = threadIdx.x, lane = tid & 31, w = tid >> 5;
    float* prw = pr + w * 400;

    for (int j = w; j < SS; j += 8) {
        ks[j * 34 + lane] = k[base + (long)j * DD + lane];
        vs[j * 32 + lane] = v[base + (long)j * DD + lane];
    }
    __syncthreads();

    const float scale = 0.1767766952966369f; // 1/sqrt(32)

    for (int pp = w; pp < SS / 2; pp += 8) {
        int i0 = 2 * pp, i1 = i0 + 1;

        // q rows packed as f32x2 over head-dim pairs
        ull q2a[16], q2b[16];
        const float* qp0 = q + base + (long)i0 * DD;
        #pragma unroll
        for (int dp = 0; dp < 16; dp++) {
            q2a[dp] = *(const ull*)(qp0 + 2 * dp);
            q2b[dp] = *(const ull*)(qp0 + DD + 2 * dp);
        }

        // ---- scores (each ks read feeds both queries) ----
        float mx0 = -1e30f, mx1 = -1e30f;
        for (int j = lane; j <= i1; j += 32) {
            ull s2a = 0ull, s2b = 0ull;
            const float* kr = ks + j * 34;
            #pragma unroll
            for (int dp = 0; dp < 16; dp++) {
                ull kk = *(const ull*)(kr + 2 * dp);   // 8B-aligned (stride 34)
                fma2(s2a, q2a[dp], kk);
                fma2(s2b, q2b[dp], kk);
            }
            float2 fa = unpack2(s2a), fb = unpack2(s2b);
            float s0 = (fa.x + fa.y) * scale;
            float s1 = (fb.x + fb.y) * scale;
            if (j > i0) s0 = -1e30f;          // causal mask for query i0
            prw[2 * j]     = s0;
            prw[2 * j + 1] = s1;
            mx0 = fmaxf(mx0, s0);
            mx1 = fmaxf(mx1, s1);
        }
        #pragma unroll
        for (int oo = 16; oo; oo >>= 1) {
            mx0 = fmaxf(mx0, __shfl_xor_sync(0xffffffffu, mx0, oo));
            mx1 = fmaxf(mx1, __shfl_xor_sync(0xffffffffu, mx1, oo));
        }

        float sum0 = 0.f, sum1 = 0.f;
        for (int j = lane; j <= i1; j += 32) {
            float e0 = __expf(prw[2 * j]     - mx0);
            float e1 = __expf(prw[2 * j + 1] - mx1);
            prw[2 * j]     = e0;
            prw[2 * j + 1] = e1;
            sum0 += e0; sum1 += e1;
        }
        #pragma unroll
        for (int oo = 16; oo; oo >>= 1) {
            sum0 += __shfl_xor_sync(0xffffffffu, sum0, oo);
            sum1 += __shfl_xor_sync(0xffffffffu, sum1, oo);
        }
        float inv0 = 1.0f / sum0, inv1 = 1.0f / sum1;
        __syncwarp();

        // ---- ctx: lane = head dim; each vs read feeds both queries ----
        ull acc2 = 0ull;                    // (acc_i0, acc_i1)
        for (int j = 0; j <= i1; j += 2) {  // i1 odd -> exact pairs
            float4 p4 = *(const float4*)(prw + 2 * j);  // (p0_j, p1_j, p0_j1, p1_j1)
            float va = vs[j * 32 + lane];
            float vb = vs[(j + 1) * 32 + lane];
            fma2(acc2, pack2(p4.x, p4.y), pack2(va, va));
            fma2(acc2, pack2(p4.z, p4.w), pack2(vb, vb));
        }
        float2 a2 = unpack2(acc2);
        o[base + (long)i0 * DD + lane] = a2.x * inv0;
        o[base + (long)i1 * DD + lane] = a2.y * inv1;
        __syncwarp();
    }
}

// ================= Gram: out[64][64] += sum_n X[n][i]*X[n][j] =================
__global__ __launch_bounds__(256) void gram_kernel(
    const float* __restrict__ X, int nrows, float* __restrict__ out)
{
    __shared__ float rs[32][65];
    int tid = threadIdx.x, tx = tid & 15, ty = tid >> 4;
    float acc[4][4] = {};
    int ntiles = (nrows + 31) / 32;
    for (int tile = blockIdx.x; tile < ntiles; tile += gridDim.x) {
        long r0 = (long)tile * 32;
        __syncthreads();
        #pragma unroll
        for (int kk = 0; kk < 2; kk++) {
            int e = tid + 256 * kk;
            int row = e >> 4, c4 = (e & 15) * 4;
            long gr = r0 + row;
            float4 a4 = (gr < nrows) ? *(const float4*)(X + gr * 64 + c4)
                                     : make_float4(0.f, 0.f, 0.f, 0.f);
            rs[row][c4 + 0] = a4.x; rs[row][c4 + 1] = a4.y;
            rs[row][c4 + 2] = a4.z; rs[row][c4 + 3] = a4.w;
        }
        __syncthreads();
        #pragma unroll 8
        for (int n = 0; n < 32; n++) {
            float a0 = rs[n][ty],      a1 = rs[n][ty + 16];
            float a2 = rs[n][ty + 32], a3 = rs[n][ty + 48];
            float b0 = rs[n][tx],      b1 = rs[n][tx + 16];
            float b2 = rs[n][tx + 32], b3 = rs[n][tx + 48];
            acc[0][0] += a0 * b0; acc[0][1] += a0 * b1; acc[0][2] += a0 * b2; acc[0][3] += a0 * b3;
            acc[1][0] += a1 * b0; acc[1][1] += a1 * b1; acc[1][2] += a1 * b2; acc[1][3] += a1 * b3;
            acc[2][0] += a2 * b0; acc[2][1] += a2 * b1; acc[2][2] += a2 * b2; acc[2][3] += a2 * b3;
            acc[3][0] += a3 * b0; acc[3][1] += a3 * b1; acc[3][2] += a3 * b2; acc[3][3] += a3 * b3;
        }
    }
    #pragma unroll
    for (int r = 0; r < 4; r++)
        #pragma unroll
        for (int c = 0; c < 4; c++)
            atomicAdd(out + (ty + 16 * r) * 64 + (tx + 16 * c), acc[r][c]);
}

// ================= right term =================
__global__ __launch_bounds__(256) void right_kernel(
    const float* __restrict__ x, const int* __restrict__ pos,
    const float* __restrict__ ie, const float* __restrict__ pw,
    float* __restrict__ slot)
{
    int lane = threadIdx.x & 31;
    int gw = blockIdx.x * 8 + (threadIdx.x >> 5);
    int nw = gridDim.x * 8;
    float2 pw2 = ((const float2*)pw)[lane];
    const float omc = 1.0f - 0.001f;
    float acc = 0.0f;
    for (int t = gw; t < BS; t += nw) {
        int idx = pos[t];
        float2 xv = ((const float2*)(x + (long)t * DD))[lane];
        float2 ev = ((const float2*)(ie + (long)idx * DD))[lane];
        float p = xv.x * ev.x * pw2.x + xv.y * ev.y * pw2.y;
        #pragma unroll
        for (int o = 16; o; o >>= 1) p += __shfl_xor_sync(0xffffffffu, p, o);
        if (lane == 0) acc += omc * p * p - 2.0f * p;
    }
    if (lane == 0) atomicAdd(slot, acc);
}

// ================= sum of squares (big tensor, atomic) =================
__global__ __launch_bounds__(256) void sumsq_kernel(
    const float* __restrict__ p, long n, float* __restrict__ slot)
{
    __shared__ float red[256];
    float acc = 0.0f;
    for (long i = (long)blockIdx.x * blockDim.x + threadIdx.x; i < n;
         i += (long)gridDim.x * blockDim.x) {
        float v = p[i];
        acc += v * v;
    }
    red[threadIdx.x] = acc;
    __syncthreads();
    for (int s = 128; s > 0; s >>= 1) {
        if (threadIdx.x < s) red[threadIdx.x] += red[threadIdx.x + s];
        __syncthreads();
    }
    if (threadIdx.x == 0) atomicAdd(slot, red[0]);
}

// ================= per-tensor-slice sumsq jobs (one block per job) =================
struct NJobs { const float* p[30]; int n[30]; };

__global__ __launch_bounds__(256) void normjobs_kernel(NJobs jobs, float* __restrict__ slots)
{
    __shared__ float red[256];
    int jb = blockIdx.x;
    const float* p = jobs.p[jb];
    int n = jobs.n[jb];
    float acc = 0.0f;
    for (int i = threadIdx.x; i < n; i += 256) {
        float v = p[i];
        acc += v * v;
    }
    red[threadIdx.x] = acc;
    __syncthreads();
    for (int s = 128; s > 0; s >>= 1) {
        if (threadIdx.x < s) red[threadIdx.x] += red[threadIdx.x + s];
        __syncthreads();
    }
    if (threadIdx.x == 0) slots[2 + jb] = red[0];
}

// ================= final assembly =================
__global__ __launch_bounds__(256) void final_kernel(
    const float* __restrict__ FF, const float* __restrict__ EE,
    const float* __restrict__ pw, const float* __restrict__ slots,
    float* __restrict__ out)
{
    __shared__ float red[256];
    float acc = 0.0f;
    for (int e = threadIdx.x; e < 4096; e += 256) {
        int i = e >> 6, j = e & 63;
        acc += FF[e] * EE[e] * pw[i] * pw[j];
    }
    red[threadIdx.x] = acc;
    __syncthreads();
    for (int s = 128; s > 0; s >>= 1) {
        if (threadIdx.x < s) red[threadIdx.x] += red[threadIdx.x + s];
        __syncthreads();
    }
    if (threadIdx.x == 0) {
        float left = 0.001f * red[0];
        float reg = sqrtf(slots[1]);        // item_emb
        for (int j = 2; j < 32; j++) reg += sqrtf(slots[j]);
        out[0] = left + slots[0] + 0.1f * reg;
    }
}

// ================= host launcher =================
extern "C" void kernel_launch(void* const* d_in, const int* in_sizes, int n_in,
                              void* d_out, int out_size)
{
    const int*   logs   = (const int*)d_in[1];
    const int*   posq   = (const int*)d_in[2];
    const float* ie     = (const float*)d_in[3];
    const float* pe     = (const float*)d_in[4];
    const float* pw     = (const float*)d_in[5];
    const float* ln_w   = (const float*)d_in[6];
    const float* ln_b   = (const float*)d_in[7];
    const float* qkv_w  = (const float*)d_in[8];
    const float* qkv_b  = (const float*)d_in[9];
    const float* out_w  = (const float*)d_in[10];
    const float* out_b  = (const float*)d_in[11];
    const float* fc1_w  = (const float*)d_in[12];
    const float* fc1_b  = (const float*)d_in[13];
    const float* ffln_w = (const float*)d_in[14];
    const float* ffln_b = (const float*)d_in[15];
    const float* fc2_w  = (const float*)d_in[16];
    const float* fc2_b  = (const float*)d_in[17];
    const float* ffln2_w= (const float*)d_in[18];
    const float* ffln2_b= (const float*)d_in[19];
    float* out = (float*)d_out;

    float *x, *qin, *q, *k, *v, *attn, *h, *t2, *FF, *EE, *slots;
    cudaGetSymbolAddress((void**)&x,    g_x);
    cudaGetSymbolAddress((void**)&qin,  g_qin);
    cudaGetSymbolAddress((void**)&q,    g_q);
    cudaGetSymbolAddress((void**)&k,    g_k);
    cudaGetSymbolAddress((void**)&v,    g_v);
    cudaGetSymbolAddress((void**)&attn, g_attn);
    cudaGetSymbolAddress((void**)&h,    g_h);
    cudaGetSymbolAddress((void**)&t2,   g_t2);
    cudaGetSymbolAddress((void**)&FF,   g_FF);
    cudaGetSymbolAddress((void**)&EE,   g_EE);
    cudaGetSymbolAddress((void**)&slots,g_slots);

    cudaFuncSetAttribute(attn2_kernel, cudaFuncAttributeMaxDynamicSharedMemorySize, ATTN_SMEM);
    cudaFuncSetAttribute(mm_t<0>, cudaFuncAttributeMaxDynamicSharedMemorySize, MM_SMEM);
    cudaFuncSetAttribute(mm_t<1>, cudaFuncAttributeMaxDynamicSharedMemorySize, MM_SMEM);

    cudaMemsetAsync(FF, 0, 4096 * sizeof(float));
    cudaMemsetAsync(EE, 0, 4096 * sizeof(float));
    cudaMemsetAsync(slots, 0, 64 * sizeof(float));

    embed_kernel<<<1600, 256>>>(logs, ie, pe, x);

    const int MBLK = BS / 128;   // 800
    for (int l = 0; l < LL; l++) {
        const float* Wqkv = qkv_w + (long)l * 192 * 64;
        const float* bqkv = qkv_b + (long)l * 192;

        ln_kernel<<<1600, 256>>>(x, ln_w + l * 64, ln_b + l * 64, qin);
        mm_t<0><<<MBLK, 256, MM_SMEM>>>(qin, Wqkv,            bqkv,       nullptr, q);
        mm_t<0><<<MBLK, 256, MM_SMEM>>>(x,   Wqkv + 64 * 64,  bqkv + 64,  nullptr, k);
        mm_t<0><<<MBLK, 256, MM_SMEM>>>(x,   Wqkv + 128 * 64, bqkv + 128, nullptr, v);
        attn2_kernel<<<BB * HH, 256, ATTN_SMEM>>>(q, k, v, attn);
        mm_t<0><<<MBLK, 256, MM_SMEM>>>(attn, out_w + (long)l * 4096, out_b + l * 64, qin, x);
        ln2_kernel<<<1600, 256>>>(x, ffln_w + l * 64, ffln_b + l * 64,
                                  ffln2_w + l * 64, ffln2_b + l * 64, qin, t2);
        mm_t<1><<<MBLK, 256, MM_SMEM>>>(qin, fc1_w + (long)l * 4096, fc1_b + l * 64, nullptr, h);
        mm_t<0><<<MBLK, 256, MM_SMEM>>>(h,   fc2_w + (long)l * 4096, fc2_b + l * 64, t2, x);
    }

    gram_kernel<<<256, 256>>>(x,  BS,     FF);
    gram_kernel<<<256, 256>>>(ie, IEROWS, EE);
    right_kernel<<<400, 256>>>(x, posq, ie, pw, slots);           // -> slots[0]
    sumsq_kernel<<<512, 256>>>(ie, (long)IEROWS * DD, slots + 1); // -> slots[1]

    NJobs jobs;
    int ji = 0;
    jobs.p[ji] = pe; jobs.n[ji] = (SS + 1) * DD; ji++;   // pos_emb
    jobs.p[ji] = pw; jobs.n[ji] = DD;            ji++;   // pred_w
    const float* bases[14] = {ln_w, ln_b, qkv_w, qkv_b, out_w, out_b,
                              fc1_w, fc1_b, ffln_w, ffln_b, fc2_w, fc2_b,
                              ffln2_w, ffln2_b};
    const int cnts[14] = {64, 64, 192 * 64, 192, 4096, 64, 4096, 64,
                          64, 64, 4096, 64, 64, 64};
    for (int t = 0; t < 14; t++)
        for (int l = 0; l < LL; l++) {
            jobs.p[ji] = bases[t] + (long)l * cnts[t];
            jobs.n[ji] = cnts[t];
            ji++;
        }
    normjobs_kernel<<<30, 256>>>(jobs, slots);   // -> slots[2..31]

    final_kernel<<<1, 256>>>(FF, EE, pw, slots, out);
}